// round 2
// baseline (speedup 1.0000x reference)
#include <cuda_runtime.h>
#include <stdint.h>
#include <stddef.h>

#define N_NODES 100000
#define N_EDGES 600000
#define NODE_IN 387
#define HID 128
#define EDGE_DIM 7

// ---------------- device scratch (allocation-free) ----------------
__device__ float g_aggr1[(size_t)N_NODES * NODE_IN];   // 155 MB
__device__ float g_mid  [(size_t)N_NODES * HID];
__device__ float g_h1   [(size_t)N_NODES * HID];
__device__ float g_aggr2[(size_t)N_NODES * HID];
__device__ float g_h2   [(size_t)N_NODES * HID];
__device__ int   g_src[N_EDGES];
__device__ int   g_dst[N_EDGES];
__device__ int   g_is64;

// ---------------- edge index dtype detection ----------------
// JAX without x64 silently downcasts int64 -> int32; detect on-device.
__global__ void detect_idx(const void* ei) {
    if (threadIdx.x == 0 && blockIdx.x == 0) {
        const long long* p = (const long long*)ei;
        int ok = 1;
        for (int i = 0; i < 1024; i++) {
            long long v = p[i];
            if (v < 0 || v >= (long long)N_NODES) { ok = 0; break; }
        }
        g_is64 = ok;
    }
}

__global__ void convert_idx(const void* ei) {
    int is64 = g_is64;
    int stride = gridDim.x * blockDim.x;
    for (int i = blockIdx.x * blockDim.x + threadIdx.x; i < 2 * N_EDGES; i += stride) {
        int v;
        if (is64) v = (int)((const long long*)ei)[i];
        else      v = ((const int*)ei)[i];
        if (i < N_EDGES) g_src[i] = v;
        else             g_dst[i - N_EDGES] = v;
    }
}

// ---------------- vectorized copy (aggr init: h = x + sum(msg)) ----------------
__global__ void copy4(const float* __restrict__ src, float* __restrict__ dst, int n4) {
    int stride = gridDim.x * blockDim.x;
    const float4* s = (const float4*)src;
    float4* d = (float4*)dst;
    for (int i = blockIdx.x * blockDim.x + threadIdx.x; i < n4; i += stride)
        d[i] = s[i];
}

// ---------------- per-edge message + scatter-add ----------------
// msg = relu(x[src] + edge_attr @ W + b); atomicAdd into aggr[dst]
template<int D>
__global__ __launch_bounds__(256) void edge_msg(
    const float* __restrict__ xin, const float* __restrict__ eattr,
    const float* __restrict__ wg, const float* __restrict__ bg,
    float* __restrict__ aggr)
{
    __shared__ float sw[EDGE_DIM * D + D];
    float* sb = sw + EDGE_DIM * D;
    for (int i = threadIdx.x; i < EDGE_DIM * D; i += 256) sw[i] = wg[i];
    for (int i = threadIdx.x; i < D; i += 256) sb[i] = bg[i];
    __syncthreads();

    int lane = threadIdx.x & 31;
    int gw = (blockIdx.x * 256 + threadIdx.x) >> 5;
    int nw = (gridDim.x * 256) >> 5;

    for (int e = gw; e < N_EDGES; e += nw) {
        int src = g_src[e];
        int dst = g_dst[e];
        float av = (lane < EDGE_DIM) ? eattr[(size_t)e * EDGE_DIM + lane] : 0.f;
        float a0 = __shfl_sync(0xffffffffu, av, 0);
        float a1 = __shfl_sync(0xffffffffu, av, 1);
        float a2 = __shfl_sync(0xffffffffu, av, 2);
        float a3 = __shfl_sync(0xffffffffu, av, 3);
        float a4 = __shfl_sync(0xffffffffu, av, 4);
        float a5 = __shfl_sync(0xffffffffu, av, 5);
        float a6 = __shfl_sync(0xffffffffu, av, 6);
        const float* xs = xin + (size_t)src * D;
        float* ag = aggr + (size_t)dst * D;
        #pragma unroll
        for (int d = lane; d < D; d += 32) {
            float m = sb[d] + xs[d];
            m = fmaf(a0, sw[0 * D + d], m);
            m = fmaf(a1, sw[1 * D + d], m);
            m = fmaf(a2, sw[2 * D + d], m);
            m = fmaf(a3, sw[3 * D + d], m);
            m = fmaf(a4, sw[4 * D + d], m);
            m = fmaf(a5, sw[5 * D + d], m);
            m = fmaf(a6, sw[6 * D + d], m);
            atomicAdd(&ag[d], fmaxf(m, 0.f));
        }
    }
}

// ---------------- tiled GEMM: C[M,128] = relu(A[M,K] @ W[K,128] + bias) ----------------
__global__ __launch_bounds__(256) void gemm_bias_relu(
    const float* __restrict__ A, const float* __restrict__ W,
    const float* __restrict__ bias, float* __restrict__ C,
    int M, int K)
{
    __shared__ float As[32][72];   // [k][row], padded
    __shared__ float Bs[32][128];  // [k][col]

    int t = threadIdx.x;
    int tx = t & 31;        // col quad: cols 4*tx..4*tx+3
    int ty = t >> 5;        // row group: rows 8*ty..8*ty+7
    int row0 = blockIdx.x * 64;

    float acc[8][4];
    #pragma unroll
    for (int i = 0; i < 8; i++)
        #pragma unroll
        for (int j = 0; j < 4; j++) acc[i][j] = 0.f;

    int ar = t >> 2;            // 0..63
    int akq = (t & 3) * 8;      // 0,8,16,24
    int br = t >> 3;            // 0..31
    int bc = (t & 7) * 16;      // 0..112

    for (int k0 = 0; k0 < K; k0 += 32) {
        int grow = row0 + ar;
        #pragma unroll
        for (int i = 0; i < 8; i++) {
            int kk = k0 + akq + i;
            float v = 0.f;
            if (grow < M && kk < K) v = A[(size_t)grow * K + kk];
            As[akq + i][ar] = v;
        }
        {
            int kk = k0 + br;
            #pragma unroll
            for (int j = 0; j < 4; j++) {
                float4 v = make_float4(0.f, 0.f, 0.f, 0.f);
                if (kk < K) v = *(const float4*)&W[(size_t)kk * 128 + bc + 4 * j];
                *(float4*)&Bs[br][bc + 4 * j] = v;
            }
        }
        __syncthreads();
        #pragma unroll
        for (int kk = 0; kk < 32; kk++) {
            float4 b4  = *(const float4*)&Bs[kk][tx * 4];
            float4 alo = *(const float4*)&As[kk][ty * 8];
            float4 ahi = *(const float4*)&As[kk][ty * 8 + 4];
            float a[8] = {alo.x, alo.y, alo.z, alo.w, ahi.x, ahi.y, ahi.z, ahi.w};
            float b[4] = {b4.x, b4.y, b4.z, b4.w};
            #pragma unroll
            for (int i = 0; i < 8; i++)
                #pragma unroll
                for (int j = 0; j < 4; j++)
                    acc[i][j] = fmaf(a[i], b[j], acc[i][j]);
        }
        __syncthreads();
    }

    float4 bb = *(const float4*)&bias[tx * 4];
    float bv[4] = {bb.x, bb.y, bb.z, bb.w};
    #pragma unroll
    for (int i = 0; i < 8; i++) {
        int row = row0 + ty * 8 + i;
        if (row < M) {
            float4 o;
            o.x = fmaxf(acc[i][0] + bv[0], 0.f);
            o.y = fmaxf(acc[i][1] + bv[1], 0.f);
            o.z = fmaxf(acc[i][2] + bv[2], 0.f);
            o.w = fmaxf(acc[i][3] + bv[3], 0.f);
            *(float4*)&C[(size_t)row * 128 + tx * 4] = o;
        }
    }
}

// ---------------- fused edge MLP ----------------
// out[e,:] = relu([h[src]||h[dst]||ea] @ W1 + b1) @ W2 + b2
// W1 [263,128] cached in smem (padded K to 264). Each warp: 4 edges at a time.
#define KPAD 264
#define EMLP_SMEM_FLOATS (KPAD * 128 + 128 + 256 + 4 + 16 * 4 * KPAD)

__global__ __launch_bounds__(512) void edge_mlp(
    const float* __restrict__ h, const float* __restrict__ eattr,
    const float* __restrict__ w1g, const float* __restrict__ b1g,
    const float* __restrict__ w2g, const float* __restrict__ b2g,
    float* __restrict__ out)
{
    extern __shared__ float sm[];
    float* w1 = sm;                       // KPAD*128
    float* b1 = w1 + KPAD * 128;          // 128
    float* w2 = b1 + 128;                 // 256
    float* b2 = w2 + 256;                 // 4
    float* inb = b2 + 4;                  // 16 warps * 4 edges * KPAD

    int t = threadIdx.x;
    for (int i = t; i < KPAD * 128; i += 512)
        w1[i] = (i < 263 * 128) ? w1g[i] : 0.f;
    if (t < 128) b1[t] = b1g[t];
    if (t < 256) w2[t] = w2g[t];
    if (t < 2)   b2[t] = b2g[t];
    __syncthreads();

    int lane = t & 31;
    int w = t >> 5;
    float* my_in = inb + w * (4 * KPAD);
    int gw = blockIdx.x * 16 + w;
    int ngw = gridDim.x * 16;

    for (int g = gw; g < N_EDGES / 4; g += ngw) {
        int e0 = g * 4;
        // stage 4 edges: [h[src](128) | h[dst](128) | ea(7) | 0]
        #pragma unroll
        for (int s = 0; s < 4; s++) {
            int e = e0 + s;
            int src = g_src[e];
            int dst = g_dst[e];
            const float* hs = h + (size_t)src * 128;
            const float* hd = h + (size_t)dst * 128;
            float* ib = my_in + s * KPAD;
            #pragma unroll
            for (int q = 0; q < 4; q++) ib[lane + 32 * q] = hs[lane + 32 * q];
            #pragma unroll
            for (int q = 0; q < 4; q++) ib[128 + lane + 32 * q] = hd[lane + 32 * q];
            if (lane < 8) ib[256 + lane] = (lane < 7) ? eattr[(size_t)e * EDGE_DIM + lane] : 0.f;
        }
        __syncwarp();

        // hidden layer: lane owns outputs o = 4*lane .. 4*lane+3
        float acc[4][4];
        #pragma unroll
        for (int s = 0; s < 4; s++)
            #pragma unroll
            for (int j = 0; j < 4; j++) acc[s][j] = 0.f;

        #pragma unroll 2
        for (int k4 = 0; k4 < KPAD / 4; k4++) {
            float4 wv0 = *(const float4*)(w1 + (size_t)(k4 * 4 + 0) * 128 + lane * 4);
            float4 wv1 = *(const float4*)(w1 + (size_t)(k4 * 4 + 1) * 128 + lane * 4);
            float4 wv2 = *(const float4*)(w1 + (size_t)(k4 * 4 + 2) * 128 + lane * 4);
            float4 wv3 = *(const float4*)(w1 + (size_t)(k4 * 4 + 3) * 128 + lane * 4);
            #pragma unroll
            for (int s = 0; s < 4; s++) {
                float4 v = *(const float4*)(my_in + s * KPAD + k4 * 4);
                acc[s][0] = fmaf(v.x, wv0.x, acc[s][0]);
                acc[s][0] = fmaf(v.y, wv1.x, acc[s][0]);
                acc[s][0] = fmaf(v.z, wv2.x, acc[s][0]);
                acc[s][0] = fmaf(v.w, wv3.x, acc[s][0]);
                acc[s][1] = fmaf(v.x, wv0.y, acc[s][1]);
                acc[s][1] = fmaf(v.y, wv1.y, acc[s][1]);
                acc[s][1] = fmaf(v.z, wv2.y, acc[s][1]);
                acc[s][1] = fmaf(v.w, wv3.y, acc[s][1]);
                acc[s][2] = fmaf(v.x, wv0.z, acc[s][2]);
                acc[s][2] = fmaf(v.y, wv1.z, acc[s][2]);
                acc[s][2] = fmaf(v.z, wv2.z, acc[s][2]);
                acc[s][2] = fmaf(v.w, wv3.z, acc[s][2]);
                acc[s][3] = fmaf(v.x, wv0.w, acc[s][3]);
                acc[s][3] = fmaf(v.y, wv1.w, acc[s][3]);
                acc[s][3] = fmaf(v.z, wv2.w, acc[s][3]);
                acc[s][3] = fmaf(v.w, wv3.w, acc[s][3]);
            }
        }
        __syncwarp();

        // relu + 128->2 layer + warp reduction
        float4 bbv = *(const float4*)(b1 + lane * 4);
        int o = lane * 4;
        #pragma unroll
        for (int s = 0; s < 4; s++) {
            float h0 = fmaxf(acc[s][0] + bbv.x, 0.f);
            float h1v = fmaxf(acc[s][1] + bbv.y, 0.f);
            float h2v = fmaxf(acc[s][2] + bbv.z, 0.f);
            float h3 = fmaxf(acc[s][3] + bbv.w, 0.f);
            float s0 = h0 * w2[(o + 0) * 2 + 0] + h1v * w2[(o + 1) * 2 + 0]
                     + h2v * w2[(o + 2) * 2 + 0] + h3 * w2[(o + 3) * 2 + 0];
            float s1 = h0 * w2[(o + 0) * 2 + 1] + h1v * w2[(o + 1) * 2 + 1]
                     + h2v * w2[(o + 2) * 2 + 1] + h3 * w2[(o + 3) * 2 + 1];
            #pragma unroll
            for (int off = 16; off; off >>= 1) {
                s0 += __shfl_down_sync(0xffffffffu, s0, off);
                s1 += __shfl_down_sync(0xffffffffu, s1, off);
            }
            if (lane == 0) {
                out[(size_t)(e0 + s) * 2 + 0] = s0 + b2[0];
                out[(size_t)(e0 + s) * 2 + 1] = s1 + b2[1];
            }
        }
    }
}

// ---------------- launch ----------------
extern "C" void kernel_launch(void* const* d_in, const int* in_sizes, int n_in,
                              void* d_out, int out_size) {
    const float* x    = (const float*)d_in[0];
    const void*  ei   = d_in[1];
    const float* ea   = (const float*)d_in[2];
    const float* e1w  = (const float*)d_in[3];
    const float* e1b  = (const float*)d_in[4];
    const float* m1w1 = (const float*)d_in[5];
    const float* m1b1 = (const float*)d_in[6];
    const float* m1w2 = (const float*)d_in[7];
    const float* m1b2 = (const float*)d_in[8];
    const float* e2w  = (const float*)d_in[9];
    const float* e2b  = (const float*)d_in[10];
    const float* m2w1 = (const float*)d_in[11];
    const float* m2b1 = (const float*)d_in[12];
    const float* m2w2 = (const float*)d_in[13];
    const float* m2b2 = (const float*)d_in[14];
    const float* emw1 = (const float*)d_in[15];
    const float* emb1 = (const float*)d_in[16];
    const float* emw2 = (const float*)d_in[17];
    const float* emb2 = (const float*)d_in[18];
    float* out = (float*)d_out;

    float *aggr1, *mid, *h1, *aggr2, *h2;
    cudaGetSymbolAddress((void**)&aggr1, g_aggr1);
    cudaGetSymbolAddress((void**)&mid,   g_mid);
    cudaGetSymbolAddress((void**)&h1,    g_h1);
    cudaGetSymbolAddress((void**)&aggr2, g_aggr2);
    cudaGetSymbolAddress((void**)&h2,    g_h2);

    size_t emlp_smem = (size_t)EMLP_SMEM_FLOATS * sizeof(float);
    cudaFuncSetAttribute(edge_mlp, cudaFuncAttributeMaxDynamicSharedMemorySize, (int)emlp_smem);

    int gemm_grid = (N_NODES + 63) / 64;

    // index canonicalization
    detect_idx<<<1, 32>>>(ei);
    convert_idx<<<2048, 256>>>(ei);

    // conv1
    copy4<<<4096, 256>>>(x, aggr1, (N_NODES * NODE_IN) / 4);
    edge_msg<NODE_IN><<<2048, 256>>>(x, ea, e1w, e1b, aggr1);
    gemm_bias_relu<<<gemm_grid, 256>>>(aggr1, m1w1, m1b1, mid, N_NODES, NODE_IN);
    gemm_bias_relu<<<gemm_grid, 256>>>(mid, m1w2, m1b2, h1, N_NODES, HID);

    // conv2
    copy4<<<2048, 256>>>(h1, aggr2, (N_NODES * HID) / 4);
    edge_msg<HID><<<2048, 256>>>(h1, ea, e2w, e2b, aggr2);
    gemm_bias_relu<<<gemm_grid, 256>>>(aggr2, m2w1, m2b1, mid, N_NODES, HID);
    gemm_bias_relu<<<gemm_grid, 256>>>(mid, m2w2, m2b2, h2, N_NODES, HID);

    // edge MLP
    edge_mlp<<<148, 512, emlp_smem>>>(h2, ea, emw1, emb1, emw2, emb2, out);
}

// round 3
// speedup vs baseline: 1.5524x; 1.5524x over previous
#include <cuda_runtime.h>
#include <stdint.h>
#include <stddef.h>

#define N_NODES 100000
#define N_EDGES 600000
#define NODE_IN 387
#define HID 128
#define EDGE_DIM 7

// ---------------- device scratch (allocation-free) ----------------
__device__ float g_aggr1[(size_t)N_NODES * NODE_IN];   // 155 MB (reused as gA/gB later)
__device__ float g_mid  [(size_t)N_NODES * HID];
__device__ float g_h1   [(size_t)N_NODES * HID];
__device__ float g_aggr2[(size_t)N_NODES * HID];
__device__ float g_h2   [(size_t)N_NODES * HID];
__device__ int   g_src[N_EDGES];
__device__ int   g_dst[N_EDGES];
__device__ int   g_is64;

// ---------------- edge index dtype detection ----------------
__global__ void detect_idx(const void* ei) {
    if (threadIdx.x == 0 && blockIdx.x == 0) {
        const long long* p = (const long long*)ei;
        int ok = 1;
        for (int i = 0; i < 1024; i++) {
            long long v = p[i];
            if (v < 0 || v >= (long long)N_NODES) { ok = 0; break; }
        }
        g_is64 = ok;
    }
}

__global__ void convert_idx(const void* ei) {
    int is64 = g_is64;
    int stride = gridDim.x * blockDim.x;
    for (int i = blockIdx.x * blockDim.x + threadIdx.x; i < 2 * N_EDGES; i += stride) {
        int v;
        if (is64) v = (int)((const long long*)ei)[i];
        else      v = ((const int*)ei)[i];
        if (i < N_EDGES) g_src[i] = v;
        else             g_dst[i - N_EDGES] = v;
    }
}

// ---------------- vectorized copy (aggr init: h = x + sum(msg)) ----------------
__global__ void copy4(const float* __restrict__ src, float* __restrict__ dst, int n4) {
    int stride = gridDim.x * blockDim.x;
    const float4* s = (const float4*)src;
    float4* d = (float4*)dst;
    for (int i = blockIdx.x * blockDim.x + threadIdx.x; i < n4; i += stride)
        d[i] = s[i];
}

// ---------------- per-edge message + scatter-add (2 edges/warp-iter for MLP) ----------------
// msg = relu(x[src] + edge_attr @ W + b); atomicAdd into aggr[dst]
template<int D>
__global__ __launch_bounds__(256) void edge_msg(
    const float* __restrict__ xin, const float* __restrict__ eattr,
    const float* __restrict__ wg, const float* __restrict__ bg,
    float* __restrict__ aggr)
{
    __shared__ float sw[EDGE_DIM * D + D];
    float* sb = sw + EDGE_DIM * D;
    for (int i = threadIdx.x; i < EDGE_DIM * D; i += 256) sw[i] = wg[i];
    for (int i = threadIdx.x; i < D; i += 256) sb[i] = bg[i];
    __syncthreads();

    int lane = threadIdx.x & 31;
    int gw = (blockIdx.x * 256 + threadIdx.x) >> 5;
    int nw = (gridDim.x * 256) >> 5;

    for (int p = gw; p < N_EDGES / 2; p += nw) {
        int e0 = 2 * p;
        int e1 = e0 + 1;
        int s0 = g_src[e0], d0 = g_dst[e0];
        int s1 = g_src[e1], d1 = g_dst[e1];
        // 14 contiguous edge-attr floats cover both edges
        float av = (lane < 14) ? eattr[(size_t)e0 * EDGE_DIM + lane] : 0.f;
        float a00 = __shfl_sync(0xffffffffu, av, 0);
        float a01 = __shfl_sync(0xffffffffu, av, 1);
        float a02 = __shfl_sync(0xffffffffu, av, 2);
        float a03 = __shfl_sync(0xffffffffu, av, 3);
        float a04 = __shfl_sync(0xffffffffu, av, 4);
        float a05 = __shfl_sync(0xffffffffu, av, 5);
        float a06 = __shfl_sync(0xffffffffu, av, 6);
        float a10 = __shfl_sync(0xffffffffu, av, 7);
        float a11 = __shfl_sync(0xffffffffu, av, 8);
        float a12 = __shfl_sync(0xffffffffu, av, 9);
        float a13 = __shfl_sync(0xffffffffu, av, 10);
        float a14 = __shfl_sync(0xffffffffu, av, 11);
        float a15 = __shfl_sync(0xffffffffu, av, 12);
        float a16 = __shfl_sync(0xffffffffu, av, 13);

        const float* xs0 = xin + (size_t)s0 * D;
        const float* xs1 = xin + (size_t)s1 * D;
        float* ag0 = aggr + (size_t)d0 * D;
        float* ag1 = aggr + (size_t)d1 * D;

        for (int d = lane; d < D; d += 32) {
            float v0 = __ldg(&xs0[d]);
            float v1 = __ldg(&xs1[d]);
            float w0 = sw[0 * D + d], w1 = sw[1 * D + d], w2 = sw[2 * D + d];
            float w3 = sw[3 * D + d], w4 = sw[4 * D + d], w5 = sw[5 * D + d];
            float w6 = sw[6 * D + d];
            float bv = sb[d];
            float m0 = bv + v0;
            float m1 = bv + v1;
            m0 = fmaf(a00, w0, m0); m1 = fmaf(a10, w0, m1);
            m0 = fmaf(a01, w1, m0); m1 = fmaf(a11, w1, m1);
            m0 = fmaf(a02, w2, m0); m1 = fmaf(a12, w2, m1);
            m0 = fmaf(a03, w3, m0); m1 = fmaf(a13, w3, m1);
            m0 = fmaf(a04, w4, m0); m1 = fmaf(a14, w4, m1);
            m0 = fmaf(a05, w5, m0); m1 = fmaf(a15, w5, m1);
            m0 = fmaf(a06, w6, m0); m1 = fmaf(a16, w6, m1);
            atomicAdd(&ag0[d], fmaxf(m0, 0.f));
            atomicAdd(&ag1[d], fmaxf(m1, 0.f));
        }
    }
}

// ---------------- tiled GEMM: C[M,128] = act(A[M,K] @ W[K,128] (+ bias)) ----------------
template<bool RELU, bool BIAS>
__global__ __launch_bounds__(256) void gemm_k(
    const float* __restrict__ A, const float* __restrict__ W,
    const float* __restrict__ bias, float* __restrict__ C,
    int M, int K)
{
    __shared__ float As[32][72];   // [k][row], padded
    __shared__ float Bs[32][128];  // [k][col]

    int t = threadIdx.x;
    int tx = t & 31;        // col quad: cols 4*tx..4*tx+3
    int ty = t >> 5;        // row group: rows 8*ty..8*ty+7
    int row0 = blockIdx.x * 64;

    float acc[8][4];
    #pragma unroll
    for (int i = 0; i < 8; i++)
        #pragma unroll
        for (int j = 0; j < 4; j++) acc[i][j] = 0.f;

    int ar = t >> 2;            // 0..63
    int akq = (t & 3) * 8;      // 0,8,16,24
    int br = t >> 3;            // 0..31
    int bc = (t & 7) * 16;      // 0..112

    for (int k0 = 0; k0 < K; k0 += 32) {
        int grow = row0 + ar;
        #pragma unroll
        for (int i = 0; i < 8; i++) {
            int kk = k0 + akq + i;
            float v = 0.f;
            if (grow < M && kk < K) v = A[(size_t)grow * K + kk];
            As[akq + i][ar] = v;
        }
        {
            int kk = k0 + br;
            #pragma unroll
            for (int j = 0; j < 4; j++) {
                float4 v = make_float4(0.f, 0.f, 0.f, 0.f);
                if (kk < K) v = *(const float4*)&W[(size_t)kk * 128 + bc + 4 * j];
                *(float4*)&Bs[br][bc + 4 * j] = v;
            }
        }
        __syncthreads();
        #pragma unroll
        for (int kk = 0; kk < 32; kk++) {
            float4 b4  = *(const float4*)&Bs[kk][tx * 4];
            float4 alo = *(const float4*)&As[kk][ty * 8];
            float4 ahi = *(const float4*)&As[kk][ty * 8 + 4];
            float a[8] = {alo.x, alo.y, alo.z, alo.w, ahi.x, ahi.y, ahi.z, ahi.w};
            float b[4] = {b4.x, b4.y, b4.z, b4.w};
            #pragma unroll
            for (int i = 0; i < 8; i++)
                #pragma unroll
                for (int j = 0; j < 4; j++)
                    acc[i][j] = fmaf(a[i], b[j], acc[i][j]);
        }
        __syncthreads();
    }

    float bv[4] = {0.f, 0.f, 0.f, 0.f};
    if (BIAS) {
        float4 bb = *(const float4*)&bias[tx * 4];
        bv[0] = bb.x; bv[1] = bb.y; bv[2] = bb.z; bv[3] = bb.w;
    }
    #pragma unroll
    for (int i = 0; i < 8; i++) {
        int row = row0 + ty * 8 + i;
        if (row < M) {
            float4 o;
            o.x = acc[i][0] + bv[0];
            o.y = acc[i][1] + bv[1];
            o.z = acc[i][2] + bv[2];
            o.w = acc[i][3] + bv[3];
            if (RELU) {
                o.x = fmaxf(o.x, 0.f); o.y = fmaxf(o.y, 0.f);
                o.z = fmaxf(o.z, 0.f); o.w = fmaxf(o.w, 0.f);
            }
            *(float4*)&C[(size_t)row * 128 + tx * 4] = o;
        }
    }
}

// ---------------- decomposed edge MLP output stage ----------------
// hidden[e] = relu(A[src] + B[dst] + ea@Wc + b1);  out[e] = hidden @ W2 + b2
// Warp per 2 edges; lane owns hidden dims 4*lane..4*lane+3 (float4).
__global__ __launch_bounds__(512) void edge_out(
    const float* __restrict__ Arow, const float* __restrict__ Brow,
    const float* __restrict__ eattr,
    const float* __restrict__ w1g,  // full em_w1 [263,128]; Wc = rows 256..262
    const float* __restrict__ b1g,
    const float* __restrict__ w2g, const float* __restrict__ b2g,
    float* __restrict__ out)
{
    __shared__ float wc[EDGE_DIM * 128];
    __shared__ float b1s[128];
    __shared__ float w2s[256];
    __shared__ float b2s[2];

    int t = threadIdx.x;
    for (int i = t; i < EDGE_DIM * 128; i += 512) wc[i] = w1g[256 * 128 + i];
    if (t < 128) b1s[t] = b1g[t];
    if (t < 256) w2s[t] = w2g[t];
    if (t < 2)   b2s[t] = b2g[t];
    __syncthreads();

    int lane = t & 31;
    int w = t >> 5;
    int gw = blockIdx.x * 16 + w;
    int ngw = gridDim.x * 16;

    const float4* A4 = (const float4*)Arow;
    const float4* B4 = (const float4*)Brow;
    const float4* wc4 = (const float4*)wc;

    float4 bb = *(const float4*)&b1s[lane * 4];
    float w20 = w2s[(lane * 4 + 0) * 2 + 0], w21 = w2s[(lane * 4 + 0) * 2 + 1];
    float w22 = w2s[(lane * 4 + 1) * 2 + 0], w23 = w2s[(lane * 4 + 1) * 2 + 1];
    float w24 = w2s[(lane * 4 + 2) * 2 + 0], w25 = w2s[(lane * 4 + 2) * 2 + 1];
    float w26 = w2s[(lane * 4 + 3) * 2 + 0], w27 = w2s[(lane * 4 + 3) * 2 + 1];
    float bo0 = b2s[0], bo1 = b2s[1];

    for (int p = gw; p < N_EDGES / 2; p += ngw) {
        int e0 = 2 * p, e1 = e0 + 1;
        int s0 = g_src[e0], d0 = g_dst[e0];
        int s1 = g_src[e1], d1 = g_dst[e1];
        float4 va0 = A4[(size_t)s0 * 32 + lane];
        float4 vb0 = B4[(size_t)d0 * 32 + lane];
        float4 va1 = A4[(size_t)s1 * 32 + lane];
        float4 vb1 = B4[(size_t)d1 * 32 + lane];

        float av = (lane < 14) ? eattr[(size_t)e0 * EDGE_DIM + lane] : 0.f;
        float a00 = __shfl_sync(0xffffffffu, av, 0);
        float a01 = __shfl_sync(0xffffffffu, av, 1);
        float a02 = __shfl_sync(0xffffffffu, av, 2);
        float a03 = __shfl_sync(0xffffffffu, av, 3);
        float a04 = __shfl_sync(0xffffffffu, av, 4);
        float a05 = __shfl_sync(0xffffffffu, av, 5);
        float a06 = __shfl_sync(0xffffffffu, av, 6);
        float a10 = __shfl_sync(0xffffffffu, av, 7);
        float a11 = __shfl_sync(0xffffffffu, av, 8);
        float a12 = __shfl_sync(0xffffffffu, av, 9);
        float a13 = __shfl_sync(0xffffffffu, av, 10);
        float a14 = __shfl_sync(0xffffffffu, av, 11);
        float a15 = __shfl_sync(0xffffffffu, av, 12);
        float a16 = __shfl_sync(0xffffffffu, av, 13);

        float4 c0 = make_float4(0.f, 0.f, 0.f, 0.f);
        float4 c1 = make_float4(0.f, 0.f, 0.f, 0.f);
        #pragma unroll
        for (int k = 0; k < EDGE_DIM; k++) {
            float4 wv = wc4[k * 32 + lane];
            float ak0, ak1;
            switch (k) {
                case 0: ak0 = a00; ak1 = a10; break;
                case 1: ak0 = a01; ak1 = a11; break;
                case 2: ak0 = a02; ak1 = a12; break;
                case 3: ak0 = a03; ak1 = a13; break;
                case 4: ak0 = a04; ak1 = a14; break;
                case 5: ak0 = a05; ak1 = a15; break;
                default: ak0 = a06; ak1 = a16; break;
            }
            c0.x = fmaf(ak0, wv.x, c0.x); c1.x = fmaf(ak1, wv.x, c1.x);
            c0.y = fmaf(ak0, wv.y, c0.y); c1.y = fmaf(ak1, wv.y, c1.y);
            c0.z = fmaf(ak0, wv.z, c0.z); c1.z = fmaf(ak1, wv.z, c1.z);
            c0.w = fmaf(ak0, wv.w, c0.w); c1.w = fmaf(ak1, wv.w, c1.w);
        }

        float h00 = fmaxf(va0.x + vb0.x + c0.x + bb.x, 0.f);
        float h01 = fmaxf(va0.y + vb0.y + c0.y + bb.y, 0.f);
        float h02 = fmaxf(va0.z + vb0.z + c0.z + bb.z, 0.f);
        float h03 = fmaxf(va0.w + vb0.w + c0.w + bb.w, 0.f);
        float h10 = fmaxf(va1.x + vb1.x + c1.x + bb.x, 0.f);
        float h11 = fmaxf(va1.y + vb1.y + c1.y + bb.y, 0.f);
        float h12 = fmaxf(va1.z + vb1.z + c1.z + bb.z, 0.f);
        float h13 = fmaxf(va1.w + vb1.w + c1.w + bb.w, 0.f);

        float s0o = h00 * w20 + h01 * w22 + h02 * w24 + h03 * w26;
        float s1o = h00 * w21 + h01 * w23 + h02 * w25 + h03 * w27;
        float s2o = h10 * w20 + h11 * w22 + h12 * w24 + h13 * w26;
        float s3o = h10 * w21 + h11 * w23 + h12 * w25 + h13 * w27;

        #pragma unroll
        for (int off = 16; off; off >>= 1) {
            s0o += __shfl_down_sync(0xffffffffu, s0o, off);
            s1o += __shfl_down_sync(0xffffffffu, s1o, off);
            s2o += __shfl_down_sync(0xffffffffu, s2o, off);
            s3o += __shfl_down_sync(0xffffffffu, s3o, off);
        }
        if (lane == 0) {
            *(float2*)&out[(size_t)e0 * 2] = make_float2(s0o + bo0, s1o + bo1);
            *(float2*)&out[(size_t)e1 * 2] = make_float2(s2o + bo0, s3o + bo1);
        }
    }
}

// ---------------- launch ----------------
extern "C" void kernel_launch(void* const* d_in, const int* in_sizes, int n_in,
                              void* d_out, int out_size) {
    const float* x    = (const float*)d_in[0];
    const void*  ei   = d_in[1];
    const float* ea   = (const float*)d_in[2];
    const float* e1w  = (const float*)d_in[3];
    const float* e1b  = (const float*)d_in[4];
    const float* m1w1 = (const float*)d_in[5];
    const float* m1b1 = (const float*)d_in[6];
    const float* m1w2 = (const float*)d_in[7];
    const float* m1b2 = (const float*)d_in[8];
    const float* e2w  = (const float*)d_in[9];
    const float* e2b  = (const float*)d_in[10];
    const float* m2w1 = (const float*)d_in[11];
    const float* m2b1 = (const float*)d_in[12];
    const float* m2w2 = (const float*)d_in[13];
    const float* m2b2 = (const float*)d_in[14];
    const float* emw1 = (const float*)d_in[15];
    const float* emb1 = (const float*)d_in[16];
    const float* emw2 = (const float*)d_in[17];
    const float* emb2 = (const float*)d_in[18];
    float* out = (float*)d_out;

    float *aggr1, *mid, *h1, *aggr2, *h2;
    cudaGetSymbolAddress((void**)&aggr1, g_aggr1);
    cudaGetSymbolAddress((void**)&mid,   g_mid);
    cudaGetSymbolAddress((void**)&h1,    g_h1);
    cudaGetSymbolAddress((void**)&aggr2, g_aggr2);
    cudaGetSymbolAddress((void**)&h2,    g_h2);
    // reuse aggr1's 155MB as gA/gB (aggr1 dead after gemm1)
    float* gA = aggr1;
    float* gB = aggr1 + (size_t)N_NODES * HID;

    int gemm_grid = (N_NODES + 63) / 64;

    // index canonicalization
    detect_idx<<<1, 32>>>(ei);
    convert_idx<<<1024, 256>>>(ei);

    // conv1
    copy4<<<4096, 256>>>(x, aggr1, (N_NODES * NODE_IN) / 4);
    edge_msg<NODE_IN><<<2048, 256>>>(x, ea, e1w, e1b, aggr1);
    gemm_k<true, true><<<gemm_grid, 256>>>(aggr1, m1w1, m1b1, mid, N_NODES, NODE_IN);
    gemm_k<true, true><<<gemm_grid, 256>>>(mid, m1w2, m1b2, h1, N_NODES, HID);

    // conv2
    copy4<<<2048, 256>>>(h1, aggr2, (N_NODES * HID) / 4);
    edge_msg<HID><<<2048, 256>>>(h1, ea, e2w, e2b, aggr2);
    gemm_k<true, true><<<gemm_grid, 256>>>(aggr2, m2w1, m2b1, mid, N_NODES, HID);
    gemm_k<true, true><<<gemm_grid, 256>>>(mid, m2w2, m2b2, h2, N_NODES, HID);

    // edge MLP (decomposed): gA = h2@W1[0:128], gB = h2@W1[128:256]
    gemm_k<false, false><<<gemm_grid, 256>>>(h2, emw1, nullptr, gA, N_NODES, HID);
    gemm_k<false, false><<<gemm_grid, 256>>>(h2, emw1 + 128 * 128, nullptr, gB, N_NODES, HID);
    edge_out<<<296, 512>>>(gA, gB, ea, emw1, emb1, emw2, emb2, out);
}

// round 4
// speedup vs baseline: 2.1876x; 1.4092x over previous
#include <cuda_runtime.h>
#include <stdint.h>
#include <stddef.h>

#define N_NODES 100000
#define N_EDGES 600000
#define NODE_IN 387
#define HID 128
#define EDGE_DIM 7
#define CHUNK 129   // 387 = 3*129; per-pass working set 2*51.6MB < L2

// ---------------- device scratch (allocation-free) ----------------
__device__ float g_aggr1[(size_t)N_NODES * NODE_IN];   // 155 MB (reused as gA/gB later)
__device__ float g_mid  [(size_t)N_NODES * HID];
__device__ float g_h1   [(size_t)N_NODES * HID];
__device__ float g_aggr2[(size_t)N_NODES * HID];
__device__ float g_h2   [(size_t)N_NODES * HID];
__device__ int   g_src[N_EDGES];
__device__ int   g_dst[N_EDGES];
__device__ int   g_is64;

// ---------------- edge index dtype detection ----------------
__global__ void detect_idx(const void* ei) {
    if (threadIdx.x == 0 && blockIdx.x == 0) {
        const long long* p = (const long long*)ei;
        int ok = 1;
        for (int i = 0; i < 1024; i++) {
            long long v = p[i];
            if (v < 0 || v >= (long long)N_NODES) { ok = 0; break; }
        }
        g_is64 = ok;
    }
}

__global__ void convert_idx(const void* ei) {
    int is64 = g_is64;
    int stride = gridDim.x * blockDim.x;
    for (int i = blockIdx.x * blockDim.x + threadIdx.x; i < 2 * N_EDGES; i += stride) {
        int v;
        if (is64) v = (int)((const long long*)ei)[i];
        else      v = ((const int*)ei)[i];
        if (i < N_EDGES) g_src[i] = v;
        else             g_dst[i - N_EDGES] = v;
    }
}

// ---------------- vectorized copy ----------------
__global__ void copy4(const float* __restrict__ src, float* __restrict__ dst, int n4) {
    int stride = gridDim.x * blockDim.x;
    const float4* s = (const float4*)src;
    float4* d = (float4*)dst;
    for (int i = blockIdx.x * blockDim.x + threadIdx.x; i < n4; i += stride)
        d[i] = s[i];
}

// ---------------- conv1 message+scatter, feature-chunked for L2 residency ----------------
// aggr[dst, dlo:dlo+CHUNK] += relu(x[src, dlo:dlo+CHUNK] + ea @ W[:, dlo:dlo+CHUNK] + b)
__global__ __launch_bounds__(256) void edge_msg_chunk(
    const float* __restrict__ xin, const float* __restrict__ eattr,
    const float* __restrict__ wg, const float* __restrict__ bg,
    float* __restrict__ aggr, int dlo)
{
    __shared__ float sw[EDGE_DIM * CHUNK];
    __shared__ float sb[CHUNK];
    for (int i = threadIdx.x; i < EDGE_DIM * CHUNK; i += 256) {
        int k = i / CHUNK, j = i % CHUNK;
        sw[i] = wg[k * NODE_IN + dlo + j];
    }
    for (int i = threadIdx.x; i < CHUNK; i += 256) sb[i] = bg[dlo + i];
    __syncthreads();

    int lane = threadIdx.x & 31;
    int gw = (blockIdx.x * 256 + threadIdx.x) >> 5;
    int nw = (gridDim.x * 256) >> 5;

    for (int p = gw; p < N_EDGES / 2; p += nw) {
        int e0 = 2 * p, e1 = e0 + 1;
        int s0 = g_src[e0], d0 = g_dst[e0];
        int s1 = g_src[e1], d1 = g_dst[e1];
        float av = (lane < 14) ? eattr[(size_t)e0 * EDGE_DIM + lane] : 0.f;
        float a00 = __shfl_sync(0xffffffffu, av, 0);
        float a01 = __shfl_sync(0xffffffffu, av, 1);
        float a02 = __shfl_sync(0xffffffffu, av, 2);
        float a03 = __shfl_sync(0xffffffffu, av, 3);
        float a04 = __shfl_sync(0xffffffffu, av, 4);
        float a05 = __shfl_sync(0xffffffffu, av, 5);
        float a06 = __shfl_sync(0xffffffffu, av, 6);
        float a10 = __shfl_sync(0xffffffffu, av, 7);
        float a11 = __shfl_sync(0xffffffffu, av, 8);
        float a12 = __shfl_sync(0xffffffffu, av, 9);
        float a13 = __shfl_sync(0xffffffffu, av, 10);
        float a14 = __shfl_sync(0xffffffffu, av, 11);
        float a15 = __shfl_sync(0xffffffffu, av, 12);
        float a16 = __shfl_sync(0xffffffffu, av, 13);

        const float* xs0 = xin + (size_t)s0 * NODE_IN + dlo;
        const float* xs1 = xin + (size_t)s1 * NODE_IN + dlo;
        float* ag0 = aggr + (size_t)d0 * NODE_IN + dlo;
        float* ag1 = aggr + (size_t)d1 * NODE_IN + dlo;

        #pragma unroll
        for (int j = lane; j < CHUNK; j += 32) {
            float v0 = __ldg(&xs0[j]);
            float v1 = __ldg(&xs1[j]);
            float w0 = sw[0 * CHUNK + j], w1 = sw[1 * CHUNK + j], w2 = sw[2 * CHUNK + j];
            float w3 = sw[3 * CHUNK + j], w4 = sw[4 * CHUNK + j], w5 = sw[5 * CHUNK + j];
            float w6 = sw[6 * CHUNK + j];
            float bv = sb[j];
            float m0 = bv + v0, m1 = bv + v1;
            m0 = fmaf(a00, w0, m0); m1 = fmaf(a10, w0, m1);
            m0 = fmaf(a01, w1, m0); m1 = fmaf(a11, w1, m1);
            m0 = fmaf(a02, w2, m0); m1 = fmaf(a12, w2, m1);
            m0 = fmaf(a03, w3, m0); m1 = fmaf(a13, w3, m1);
            m0 = fmaf(a04, w4, m0); m1 = fmaf(a14, w4, m1);
            m0 = fmaf(a05, w5, m0); m1 = fmaf(a15, w5, m1);
            m0 = fmaf(a06, w6, m0); m1 = fmaf(a16, w6, m1);
            atomicAdd(&ag0[j], fmaxf(m0, 0.f));
            atomicAdd(&ag1[j], fmaxf(m1, 0.f));
        }
    }
}

// ---------------- conv2 message+scatter (D=128, L2-resident already) ----------------
__global__ __launch_bounds__(256) void edge_msg128(
    const float* __restrict__ xin, const float* __restrict__ eattr,
    const float* __restrict__ wg, const float* __restrict__ bg,
    float* __restrict__ aggr)
{
    __shared__ float sw[EDGE_DIM * HID];
    __shared__ float sb[HID];
    for (int i = threadIdx.x; i < EDGE_DIM * HID; i += 256) sw[i] = wg[i];
    if (threadIdx.x < HID) sb[threadIdx.x] = bg[threadIdx.x];
    __syncthreads();

    int lane = threadIdx.x & 31;
    int gw = (blockIdx.x * 256 + threadIdx.x) >> 5;
    int nw = (gridDim.x * 256) >> 5;

    for (int p = gw; p < N_EDGES / 2; p += nw) {
        int e0 = 2 * p, e1 = e0 + 1;
        int s0 = g_src[e0], d0 = g_dst[e0];
        int s1 = g_src[e1], d1 = g_dst[e1];
        float av = (lane < 14) ? eattr[(size_t)e0 * EDGE_DIM + lane] : 0.f;
        float a00 = __shfl_sync(0xffffffffu, av, 0);
        float a01 = __shfl_sync(0xffffffffu, av, 1);
        float a02 = __shfl_sync(0xffffffffu, av, 2);
        float a03 = __shfl_sync(0xffffffffu, av, 3);
        float a04 = __shfl_sync(0xffffffffu, av, 4);
        float a05 = __shfl_sync(0xffffffffu, av, 5);
        float a06 = __shfl_sync(0xffffffffu, av, 6);
        float a10 = __shfl_sync(0xffffffffu, av, 7);
        float a11 = __shfl_sync(0xffffffffu, av, 8);
        float a12 = __shfl_sync(0xffffffffu, av, 9);
        float a13 = __shfl_sync(0xffffffffu, av, 10);
        float a14 = __shfl_sync(0xffffffffu, av, 11);
        float a15 = __shfl_sync(0xffffffffu, av, 12);
        float a16 = __shfl_sync(0xffffffffu, av, 13);

        const float* xs0 = xin + (size_t)s0 * HID;
        const float* xs1 = xin + (size_t)s1 * HID;
        float* ag0 = aggr + (size_t)d0 * HID;
        float* ag1 = aggr + (size_t)d1 * HID;

        #pragma unroll
        for (int d = lane; d < HID; d += 32) {
            float v0 = __ldg(&xs0[d]);
            float v1 = __ldg(&xs1[d]);
            float w0 = sw[0 * HID + d], w1 = sw[1 * HID + d], w2 = sw[2 * HID + d];
            float w3 = sw[3 * HID + d], w4 = sw[4 * HID + d], w5 = sw[5 * HID + d];
            float w6 = sw[6 * HID + d];
            float bv = sb[d];
            float m0 = bv + v0, m1 = bv + v1;
            m0 = fmaf(a00, w0, m0); m1 = fmaf(a10, w0, m1);
            m0 = fmaf(a01, w1, m0); m1 = fmaf(a11, w1, m1);
            m0 = fmaf(a02, w2, m0); m1 = fmaf(a12, w2, m1);
            m0 = fmaf(a03, w3, m0); m1 = fmaf(a13, w3, m1);
            m0 = fmaf(a04, w4, m0); m1 = fmaf(a14, w4, m1);
            m0 = fmaf(a05, w5, m0); m1 = fmaf(a15, w5, m1);
            m0 = fmaf(a06, w6, m0); m1 = fmaf(a16, w6, m1);
            atomicAdd(&ag0[d], fmaxf(m0, 0.f));
            atomicAdd(&ag1[d], fmaxf(m1, 0.f));
        }
    }
}

// ---------------- tf32 tensor-core GEMM: C[M,128] = act(A[M,K]@W[K,128] (+bias)) ----------------
__device__ __forceinline__ uint32_t f2tf32(float f) {
    uint32_t u;
    asm("cvt.rna.tf32.f32 %0, %1;" : "=r"(u) : "f"(f));
    return u;
}

template<bool RELU, bool BIAS>
__global__ __launch_bounds__(256) void gemm_tc(
    const float* __restrict__ A, const float* __restrict__ W,
    const float* __restrict__ bias, float* __restrict__ C,
    int M, int K)
{
    __shared__ uint32_t As[128][36];   // [m][k], pad 36 -> frag loads conflict-free
    __shared__ uint32_t Bs[32][132];   // [k][n], pad 132 -> frag loads conflict-free

    int t = threadIdx.x;
    int lane = t & 31;
    int warp = t >> 5;
    int wm = warp & 3;    // 32-row strip
    int wn = warp >> 2;   // 64-col strip
    int row0 = blockIdx.x * 128;
    bool k4 = (K & 3) == 0;

    float c[2][8][4];
    #pragma unroll
    for (int mt = 0; mt < 2; mt++)
        #pragma unroll
        for (int nt = 0; nt < 8; nt++)
            #pragma unroll
            for (int i = 0; i < 4; i++) c[mt][nt][i] = 0.f;

    for (int k0 = 0; k0 < K; k0 += 32) {
        // load A tile: 128 x 32
        #pragma unroll
        for (int i = 0; i < 4; i++) {
            int idx = t + i * 256;         // 0..1023
            int r = idx >> 3;
            int kq = (idx & 7) * 4;
            int gr = row0 + r;
            int gk = k0 + kq;
            float4 v = make_float4(0.f, 0.f, 0.f, 0.f);
            if (gr < M) {
                if (k4 && gk + 3 < K) {
                    v = *(const float4*)&A[(size_t)gr * K + gk];
                } else {
                    float tv[4] = {0.f, 0.f, 0.f, 0.f};
                    #pragma unroll
                    for (int j = 0; j < 4; j++)
                        if (gk + j < K) tv[j] = __ldg(&A[(size_t)gr * K + gk + j]);
                    v = make_float4(tv[0], tv[1], tv[2], tv[3]);
                }
            }
            uint4 u = make_uint4(f2tf32(v.x), f2tf32(v.y), f2tf32(v.z), f2tf32(v.w));
            *(uint4*)&As[r][kq] = u;
        }
        // load B tile: 32 x 128 (natural [k][n])
        #pragma unroll
        for (int i = 0; i < 4; i++) {
            int idx = t + i * 256;
            int kk = idx >> 5;
            int nq = (idx & 31) * 4;
            float4 v = make_float4(0.f, 0.f, 0.f, 0.f);
            if (k0 + kk < K) v = *(const float4*)&W[(size_t)(k0 + kk) * 128 + nq];
            uint4 u = make_uint4(f2tf32(v.x), f2tf32(v.y), f2tf32(v.z), f2tf32(v.w));
            *(uint4*)&Bs[kk][nq] = u;
        }
        __syncthreads();

        #pragma unroll
        for (int k8 = 0; k8 < 4; k8++) {
            int kb = k8 * 8;
            int g = lane >> 2;
            int tt = lane & 3;
            uint32_t a[2][4], b[8][2];
            #pragma unroll
            for (int mt = 0; mt < 2; mt++) {
                int ar = wm * 32 + mt * 16 + g;
                a[mt][0] = As[ar][kb + tt];
                a[mt][1] = As[ar + 8][kb + tt];
                a[mt][2] = As[ar][kb + tt + 4];
                a[mt][3] = As[ar + 8][kb + tt + 4];
            }
            #pragma unroll
            for (int nt = 0; nt < 8; nt++) {
                int bn = wn * 64 + nt * 8 + g;
                b[nt][0] = Bs[kb + tt][bn];
                b[nt][1] = Bs[kb + tt + 4][bn];
            }
            #pragma unroll
            for (int mt = 0; mt < 2; mt++)
                #pragma unroll
                for (int nt = 0; nt < 8; nt++) {
                    asm volatile(
                        "mma.sync.aligned.m16n8k8.row.col.f32.tf32.tf32.f32 "
                        "{%0,%1,%2,%3}, {%4,%5,%6,%7}, {%8,%9}, {%0,%1,%2,%3};\n"
                        : "+f"(c[mt][nt][0]), "+f"(c[mt][nt][1]),
                          "+f"(c[mt][nt][2]), "+f"(c[mt][nt][3])
                        : "r"(a[mt][0]), "r"(a[mt][1]), "r"(a[mt][2]), "r"(a[mt][3]),
                          "r"(b[nt][0]), "r"(b[nt][1]));
                }
        }
        __syncthreads();
    }

    // epilogue
    int g = lane >> 2;
    int tt = lane & 3;
    #pragma unroll
    for (int nt = 0; nt < 8; nt++) {
        int col = wn * 64 + nt * 8 + 2 * tt;
        float b0 = 0.f, b1 = 0.f;
        if (BIAS) { b0 = __ldg(&bias[col]); b1 = __ldg(&bias[col + 1]); }
        #pragma unroll
        for (int mt = 0; mt < 2; mt++) {
            int r = row0 + wm * 32 + mt * 16 + g;
            float v0 = c[mt][nt][0] + b0;
            float v1 = c[mt][nt][1] + b1;
            float v2 = c[mt][nt][2] + b0;
            float v3 = c[mt][nt][3] + b1;
            if (RELU) {
                v0 = fmaxf(v0, 0.f); v1 = fmaxf(v1, 0.f);
                v2 = fmaxf(v2, 0.f); v3 = fmaxf(v3, 0.f);
            }
            if (r < M)     *(float2*)&C[(size_t)r * 128 + col]       = make_float2(v0, v1);
            if (r + 8 < M) *(float2*)&C[(size_t)(r + 8) * 128 + col] = make_float2(v2, v3);
        }
    }
}

// ---------------- decomposed edge MLP output stage ----------------
__global__ __launch_bounds__(512) void edge_out(
    const float* __restrict__ Arow, const float* __restrict__ Brow,
    const float* __restrict__ eattr,
    const float* __restrict__ w1g,  // full em_w1 [263,128]; Wc = rows 256..262
    const float* __restrict__ b1g,
    const float* __restrict__ w2g, const float* __restrict__ b2g,
    float* __restrict__ out)
{
    __shared__ float wc[EDGE_DIM * 128];
    __shared__ float b1s[128];
    __shared__ float w2s[256];
    __shared__ float b2s[2];

    int t = threadIdx.x;
    for (int i = t; i < EDGE_DIM * 128; i += 512) wc[i] = w1g[256 * 128 + i];
    if (t < 128) b1s[t] = b1g[t];
    if (t < 256) w2s[t] = w2g[t];
    if (t < 2)   b2s[t] = b2g[t];
    __syncthreads();

    int lane = t & 31;
    int w = t >> 5;
    int gw = blockIdx.x * 16 + w;
    int ngw = gridDim.x * 16;

    const float4* A4 = (const float4*)Arow;
    const float4* B4 = (const float4*)Brow;
    const float4* wc4 = (const float4*)wc;

    float4 bb = *(const float4*)&b1s[lane * 4];
    float w20 = w2s[(lane * 4 + 0) * 2 + 0], w21 = w2s[(lane * 4 + 0) * 2 + 1];
    float w22 = w2s[(lane * 4 + 1) * 2 + 0], w23 = w2s[(lane * 4 + 1) * 2 + 1];
    float w24 = w2s[(lane * 4 + 2) * 2 + 0], w25 = w2s[(lane * 4 + 2) * 2 + 1];
    float w26 = w2s[(lane * 4 + 3) * 2 + 0], w27 = w2s[(lane * 4 + 3) * 2 + 1];
    float bo0 = b2s[0], bo1 = b2s[1];

    for (int p = gw; p < N_EDGES / 2; p += ngw) {
        int e0 = 2 * p, e1 = e0 + 1;
        int s0 = g_src[e0], d0 = g_dst[e0];
        int s1 = g_src[e1], d1 = g_dst[e1];
        float4 va0 = A4[(size_t)s0 * 32 + lane];
        float4 vb0 = B4[(size_t)d0 * 32 + lane];
        float4 va1 = A4[(size_t)s1 * 32 + lane];
        float4 vb1 = B4[(size_t)d1 * 32 + lane];

        float av = (lane < 14) ? eattr[(size_t)e0 * EDGE_DIM + lane] : 0.f;
        float a00 = __shfl_sync(0xffffffffu, av, 0);
        float a01 = __shfl_sync(0xffffffffu, av, 1);
        float a02 = __shfl_sync(0xffffffffu, av, 2);
        float a03 = __shfl_sync(0xffffffffu, av, 3);
        float a04 = __shfl_sync(0xffffffffu, av, 4);
        float a05 = __shfl_sync(0xffffffffu, av, 5);
        float a06 = __shfl_sync(0xffffffffu, av, 6);
        float a10 = __shfl_sync(0xffffffffu, av, 7);
        float a11 = __shfl_sync(0xffffffffu, av, 8);
        float a12 = __shfl_sync(0xffffffffu, av, 9);
        float a13 = __shfl_sync(0xffffffffu, av, 10);
        float a14 = __shfl_sync(0xffffffffu, av, 11);
        float a15 = __shfl_sync(0xffffffffu, av, 12);
        float a16 = __shfl_sync(0xffffffffu, av, 13);

        float4 c0 = make_float4(0.f, 0.f, 0.f, 0.f);
        float4 c1 = make_float4(0.f, 0.f, 0.f, 0.f);
        #pragma unroll
        for (int k = 0; k < EDGE_DIM; k++) {
            float4 wv = wc4[k * 32 + lane];
            float ak0, ak1;
            switch (k) {
                case 0: ak0 = a00; ak1 = a10; break;
                case 1: ak0 = a01; ak1 = a11; break;
                case 2: ak0 = a02; ak1 = a12; break;
                case 3: ak0 = a03; ak1 = a13; break;
                case 4: ak0 = a04; ak1 = a14; break;
                case 5: ak0 = a05; ak1 = a15; break;
                default: ak0 = a06; ak1 = a16; break;
            }
            c0.x = fmaf(ak0, wv.x, c0.x); c1.x = fmaf(ak1, wv.x, c1.x);
            c0.y = fmaf(ak0, wv.y, c0.y); c1.y = fmaf(ak1, wv.y, c1.y);
            c0.z = fmaf(ak0, wv.z, c0.z); c1.z = fmaf(ak1, wv.z, c1.z);
            c0.w = fmaf(ak0, wv.w, c0.w); c1.w = fmaf(ak1, wv.w, c1.w);
        }

        float h00 = fmaxf(va0.x + vb0.x + c0.x + bb.x, 0.f);
        float h01 = fmaxf(va0.y + vb0.y + c0.y + bb.y, 0.f);
        float h02 = fmaxf(va0.z + vb0.z + c0.z + bb.z, 0.f);
        float h03 = fmaxf(va0.w + vb0.w + c0.w + bb.w, 0.f);
        float h10 = fmaxf(va1.x + vb1.x + c1.x + bb.x, 0.f);
        float h11 = fmaxf(va1.y + vb1.y + c1.y + bb.y, 0.f);
        float h12 = fmaxf(va1.z + vb1.z + c1.z + bb.z, 0.f);
        float h13 = fmaxf(va1.w + vb1.w + c1.w + bb.w, 0.f);

        float s0o = h00 * w20 + h01 * w22 + h02 * w24 + h03 * w26;
        float s1o = h00 * w21 + h01 * w23 + h02 * w25 + h03 * w27;
        float s2o = h10 * w20 + h11 * w22 + h12 * w24 + h13 * w26;
        float s3o = h10 * w21 + h11 * w23 + h12 * w25 + h13 * w27;

        #pragma unroll
        for (int off = 16; off; off >>= 1) {
            s0o += __shfl_down_sync(0xffffffffu, s0o, off);
            s1o += __shfl_down_sync(0xffffffffu, s1o, off);
            s2o += __shfl_down_sync(0xffffffffu, s2o, off);
            s3o += __shfl_down_sync(0xffffffffu, s3o, off);
        }
        if (lane == 0) {
            *(float2*)&out[(size_t)e0 * 2] = make_float2(s0o + bo0, s1o + bo1);
            *(float2*)&out[(size_t)e1 * 2] = make_float2(s2o + bo0, s3o + bo1);
        }
    }
}

// ---------------- launch ----------------
extern "C" void kernel_launch(void* const* d_in, const int* in_sizes, int n_in,
                              void* d_out, int out_size) {
    const float* x    = (const float*)d_in[0];
    const void*  ei   = d_in[1];
    const float* ea   = (const float*)d_in[2];
    const float* e1w  = (const float*)d_in[3];
    const float* e1b  = (const float*)d_in[4];
    const float* m1w1 = (const float*)d_in[5];
    const float* m1b1 = (const float*)d_in[6];
    const float* m1w2 = (const float*)d_in[7];
    const float* m1b2 = (const float*)d_in[8];
    const float* e2w  = (const float*)d_in[9];
    const float* e2b  = (const float*)d_in[10];
    const float* m2w1 = (const float*)d_in[11];
    const float* m2b1 = (const float*)d_in[12];
    const float* m2w2 = (const float*)d_in[13];
    const float* m2b2 = (const float*)d_in[14];
    const float* emw1 = (const float*)d_in[15];
    const float* emb1 = (const float*)d_in[16];
    const float* emw2 = (const float*)d_in[17];
    const float* emb2 = (const float*)d_in[18];
    float* out = (float*)d_out;

    float *aggr1, *mid, *h1, *aggr2, *h2;
    cudaGetSymbolAddress((void**)&aggr1, g_aggr1);
    cudaGetSymbolAddress((void**)&mid,   g_mid);
    cudaGetSymbolAddress((void**)&h1,    g_h1);
    cudaGetSymbolAddress((void**)&aggr2, g_aggr2);
    cudaGetSymbolAddress((void**)&h2,    g_h2);
    float* gA = aggr1;                                  // reuse aggr1 after conv1
    float* gB = aggr1 + (size_t)N_NODES * HID;

    int gemm_grid = (N_NODES + 127) / 128;

    detect_idx<<<1, 32>>>(ei);
    convert_idx<<<1024, 256>>>(ei);

    // conv1 (feature-chunked scatter for L2 residency)
    copy4<<<4096, 256>>>(x, aggr1, (N_NODES * NODE_IN) / 4);
    edge_msg_chunk<<<2048, 256>>>(x, ea, e1w, e1b, aggr1, 0);
    edge_msg_chunk<<<2048, 256>>>(x, ea, e1w, e1b, aggr1, CHUNK);
    edge_msg_chunk<<<2048, 256>>>(x, ea, e1w, e1b, aggr1, 2 * CHUNK);
    gemm_tc<true, true><<<gemm_grid, 256>>>(aggr1, m1w1, m1b1, mid, N_NODES, NODE_IN);
    gemm_tc<true, true><<<gemm_grid, 256>>>(mid, m1w2, m1b2, h1, N_NODES, HID);

    // conv2
    copy4<<<2048, 256>>>(h1, aggr2, (N_NODES * HID) / 4);
    edge_msg128<<<2048, 256>>>(h1, ea, e2w, e2b, aggr2);
    gemm_tc<true, true><<<gemm_grid, 256>>>(aggr2, m2w1, m2b1, mid, N_NODES, HID);
    gemm_tc<true, true><<<gemm_grid, 256>>>(mid, m2w2, m2b2, h2, N_NODES, HID);

    // edge MLP (decomposed)
    gemm_tc<false, false><<<gemm_grid, 256>>>(h2, emw1, nullptr, gA, N_NODES, HID);
    gemm_tc<false, false><<<gemm_grid, 256>>>(h2, emw1 + 128 * 128, nullptr, gB, N_NODES, HID);
    edge_out<<<296, 512>>>(gA, gB, ea, emw1, emb1, emw2, emb2, out);
}